// round 6
// baseline (speedup 1.0000x reference)
#include <cuda_runtime.h>
#include <cuda_bf16.h>
#include <cstdint>

#define NN 1024
#define DD 128

// ---------------- scratch (no allocations allowed) ----------------
__device__ float g_q[NN * DD];
__device__ float g_k[NN * DD];
__device__ float g_att[NN * DD];
__device__ float g_gi[NN * 3 * DD];

// ---------------- helpers ----------------
__device__ __forceinline__ float tanh_apx(float x) {
    float y;
    asm("tanh.approx.f32 %0, %1;" : "=f"(y) : "f"(x));
    return y;
}

// accurate sigmoid/tanh for the GRU (errors compound over 1024 steps)
__device__ __forceinline__ float sig_acc(float x) {
    float e = __expf(-x);
    return __fdividef(1.0f, 1.0f + e);
}
__device__ __forceinline__ float tanh_acc(float x) {
    float e = __expf(-2.0f * x);
    return __fdividef(1.0f - e, 1.0f + e);
}

__device__ __forceinline__ float block_reduce_max(float v) {
    __shared__ float red[8];
    #pragma unroll
    for (int o = 16; o; o >>= 1) v = fmaxf(v, __shfl_xor_sync(0xffffffffu, v, o));
    if ((threadIdx.x & 31) == 0) red[threadIdx.x >> 5] = v;
    __syncthreads();
    float r = red[0];
    #pragma unroll
    for (int i = 1; i < 8; i++) r = fmaxf(r, red[i]);
    __syncthreads();
    return r;
}

__device__ __forceinline__ float block_reduce_sum(float v) {
    __shared__ float red[8];
    #pragma unroll
    for (int o = 16; o; o >>= 1) v += __shfl_xor_sync(0xffffffffu, v, o);
    if ((threadIdx.x & 31) == 0) red[threadIdx.x >> 5] = v;
    __syncthreads();
    float r = red[0];
    #pragma unroll
    for (int i = 1; i < 8; i++) r += red[i];
    __syncthreads();
    return r;
}

// bf16x2 packers for the hi/lo exact split
__device__ __forceinline__ uint32_t pack_hi(float2 p) {
    __nv_bfloat162 v;
    v.x = __float2bfloat16_rn(p.x);
    v.y = __float2bfloat16_rn(p.y);
    return *(uint32_t*)&v;
}
__device__ __forceinline__ uint32_t pack_lo(float2 p) {
    __nv_bfloat162 v;
    v.x = __float2bfloat16_rn(p.x - __bfloat162float(__float2bfloat16_rn(p.x)));
    v.y = __float2bfloat16_rn(p.y - __bfloat162float(__float2bfloat16_rn(p.y)));
    return *(uint32_t*)&v;
}

// m16n8k16 bf16 mma, D accumulate in fp32
__device__ __forceinline__ void mma16816(float d[4], const uint32_t a[4],
                                         const uint32_t b[2]) {
    asm volatile(
        "mma.sync.aligned.m16n8k16.row.col.f32.bf16.bf16.f32 "
        "{%0,%1,%2,%3}, {%4,%5,%6,%7}, {%8,%9}, {%0,%1,%2,%3};"
        : "+f"(d[0]), "+f"(d[1]), "+f"(d[2]), "+f"(d[3])
        : "r"(a[0]), "r"(a[1]), "r"(a[2]), "r"(a[3]), "r"(b[0]), "r"(b[1]));
}

// ---------------- kernel 1: q = X@Wq^T, k = X@Wk^T ----------------
__global__ void __launch_bounds__(256) qk_kernel(const float* __restrict__ X,
                                                 const float* __restrict__ Wq,
                                                 const float* __restrict__ Wk) {
    __shared__ __align__(16) float xs[8][DD];
    const int n0 = blockIdx.x * 8;
    const int tid = threadIdx.x;
    for (int idx = tid; idx < 8 * DD; idx += 256)
        xs[idx >> 7][idx & 127] = X[(n0 + (idx >> 7)) * DD + (idx & 127)];
    __syncthreads();

    const int s = tid >> 7;
    const int d = tid & 127;
    const float4* W4 = (const float4*)((s ? Wk : Wq) + d * DD);
    float acc[8];
    #pragma unroll
    for (int r = 0; r < 8; r++) acc[r] = 0.0f;

    #pragma unroll 8
    for (int c = 0; c < 32; c++) {
        float4 w = W4[c];
        #pragma unroll
        for (int r = 0; r < 8; r++) {
            float4 x = *(const float4*)&xs[r][c * 4];
            acc[r] += w.x * x.x + w.y * x.y + w.z * x.z + w.w * x.w;
        }
    }
    float* dst = s ? g_k : g_q;
    #pragma unroll
    for (int r = 0; r < 8; r++) dst[(n0 + r) * DD + d] = acc[r];
}

// ---------------- kernel 2: attention (scores + softmax + att) ----------------
__global__ void __launch_bounds__(256) att_kernel(const float* __restrict__ X,
                                                  const float* __restrict__ v) {
    __shared__ __align__(16) float q_s[4][DD];
    __shared__ __align__(16) float v_s[DD];
    __shared__ float sc[4][NN];
    __shared__ float inv_s[4];
    __shared__ float part[4][DD];

    const int i0 = blockIdx.x * 4;
    const int tid = threadIdx.x;

    for (int idx = tid; idx < 4 * DD; idx += 256)
        q_s[idx >> 7][idx & 127] = g_q[(i0 + (idx >> 7)) * DD + (idx & 127)];
    if (tid < DD) v_s[tid] = v[tid];
    __syncthreads();

    for (int j = i0 + tid; j < NN; j += 256) {
        const float4* kr = (const float4*)(g_k + j * DD);
        float a0 = 0.f, a1 = 0.f, a2 = 0.f, a3 = 0.f;
        #pragma unroll 4
        for (int c = 0; c < 32; c++) {
            float4 kk = kr[c];
            float4 vv = *(const float4*)&v_s[c * 4];
            float4 q0 = *(const float4*)&q_s[0][c * 4];
            float4 q1 = *(const float4*)&q_s[1][c * 4];
            float4 q2 = *(const float4*)&q_s[2][c * 4];
            float4 q3 = *(const float4*)&q_s[3][c * 4];
            a0 += vv.x * tanh_apx(q0.x + kk.x) + vv.y * tanh_apx(q0.y + kk.y)
                + vv.z * tanh_apx(q0.z + kk.z) + vv.w * tanh_apx(q0.w + kk.w);
            a1 += vv.x * tanh_apx(q1.x + kk.x) + vv.y * tanh_apx(q1.y + kk.y)
                + vv.z * tanh_apx(q1.z + kk.z) + vv.w * tanh_apx(q1.w + kk.w);
            a2 += vv.x * tanh_apx(q2.x + kk.x) + vv.y * tanh_apx(q2.y + kk.y)
                + vv.z * tanh_apx(q2.z + kk.z) + vv.w * tanh_apx(q2.w + kk.w);
            a3 += vv.x * tanh_apx(q3.x + kk.x) + vv.y * tanh_apx(q3.y + kk.y)
                + vv.z * tanh_apx(q3.z + kk.z) + vv.w * tanh_apx(q3.w + kk.w);
        }
        const int jj = j - i0;
        sc[0][jj] = a0; sc[1][jj] = a1; sc[2][jj] = a2; sc[3][jj] = a3;
    }
    __syncthreads();

    const int L = NN - i0;
    for (int r = 0; r < 4; r++) {
        float m = -1e30f;
        for (int idx = tid; idx < L; idx += 256) m = fmaxf(m, sc[r][idx]);
        const float bm = block_reduce_max(m);
        float ssum = 0.f;
        for (int idx = tid; idx < L; idx += 256) {
            float e = (idx < r) ? 0.0f : __expf(sc[r][idx] - bm);
            sc[r][idx] = e;
            ssum += e;
        }
        const float bs = block_reduce_sum(ssum);
        if (tid == 0) inv_s[r] = 1.0f / bs;
    }
    __syncthreads();

    const int d = tid & 127;
    const int s2 = tid >> 7;
    float a[4] = {0.f, 0.f, 0.f, 0.f};
    for (int j = i0 + s2; j < NN; j += 2) {
        const float x = X[j * DD + d];
        const int jj = j - i0;
        a[0] += sc[0][jj] * x;
        a[1] += sc[1][jj] * x;
        a[2] += sc[2][jj] * x;
        a[3] += sc[3][jj] * x;
    }
    if (s2) {
        #pragma unroll
        for (int r = 0; r < 4; r++) part[r][d] = a[r];
    }
    __syncthreads();
    if (!s2) {
        #pragma unroll
        for (int r = 0; r < 4; r++)
            g_att[(i0 + r) * DD + d] = (a[r] + part[r][d]) * inv_s[r];
    }
}

// ---------------- kernel 3: gi = [X, att] @ w_ih^T + b_ih (+ b_hh fold) ----
// b_hh is additive for the r and z gates (rows 0..255), so fold it here.
// The n-gate bias multiplies by r inside the GRU, so it stays separate.
__global__ void __launch_bounds__(384) gi_kernel(const float* __restrict__ X,
                                                 const float* __restrict__ w_ih,
                                                 const float* __restrict__ b_ih,
                                                 const float* __restrict__ b_hh) {
    __shared__ __align__(16) float in_s[8][2 * DD];
    const int n0 = blockIdx.x * 8;
    const int tid = threadIdx.x;
    for (int idx = tid; idx < 8 * 2 * DD; idx += 384) {
        const int n = idx >> 8, e = idx & 255;
        in_s[n][e] = (e < DD) ? X[(n0 + n) * DD + e] : g_att[(n0 + n) * DD + (e - DD)];
    }
    __syncthreads();

    const float4* w4 = (const float4*)(w_ih + tid * (2 * DD));
    float acc[8];
    #pragma unroll
    for (int r = 0; r < 8; r++) acc[r] = 0.0f;

    #pragma unroll 4
    for (int c = 0; c < 64; c++) {
        float4 w = w4[c];
        #pragma unroll
        for (int r = 0; r < 8; r++) {
            float4 iv = *(const float4*)&in_s[r][c * 4];
            acc[r] += w.x * iv.x + w.y * iv.y + w.z * iv.z + w.w * iv.w;
        }
    }
    const float b = b_ih[tid] + ((tid < 2 * DD) ? b_hh[tid] : 0.0f);
    #pragma unroll
    for (int r = 0; r < 8; r++) g_gi[(n0 + r) * 384 + tid] = acc[r] + b;
}

// ---------------- kernel 4: sequential GRU on tensor cores (mma.sync) --------
// 384 threads = 12 warps. Warp w owns gh rows [w*32, w*32+32) as two m16
// row-tiles. A-fragments (W_hi and W_lo, bf16 exact split) live in registers
// for the whole kernel. Per step, B = [h_hi | h_lo | 0...] (k16n8 fragments
// built from smem by lanes 0-7), two accumulation passes give
// D.col0 + D.col1 = (W_hi+W_lo)@(h_hi+h_lo) = W@h exactly (fp32 accumulate).
__global__ void __launch_bounds__(384, 1) gru_kernel(const float* __restrict__ w_hh,
                                                     const float* __restrict__ b_hh,
                                                     float* __restrict__ out) {
    __shared__ float gh_s[3 * DD];
    __shared__ __align__(4) __nv_bfloat16 h_hi_s[DD];
    __shared__ __align__(4) __nv_bfloat16 h_lo_s[DD];

    const int t = threadIdx.x;
    const int warp = t >> 5;
    const int lane = t & 31;
    const int qr = lane >> 2;     // quad row    (0..7)
    const int qc = lane & 3;      // quad column (0..3)

    // --- prologue: load A-fragments (W_hi, W_lo) into registers ---
    uint32_t whi[2][8][4], wlo[2][8][4];
    #pragma unroll
    for (int rt = 0; rt < 2; rt++) {
        const int r0 = warp * 32 + rt * 16 + qr;
        #pragma unroll
        for (int kk = 0; kk < 8; kk++) {
            const int c0 = kk * 16 + qc * 2;
            float2 p0 = *(const float2*)&w_hh[r0 * DD + c0];
            float2 p1 = *(const float2*)&w_hh[(r0 + 8) * DD + c0];
            float2 p2 = *(const float2*)&w_hh[r0 * DD + c0 + 8];
            float2 p3 = *(const float2*)&w_hh[(r0 + 8) * DD + c0 + 8];
            whi[rt][kk][0] = pack_hi(p0); wlo[rt][kk][0] = pack_lo(p0);
            whi[rt][kk][1] = pack_hi(p1); wlo[rt][kk][1] = pack_lo(p1);
            whi[rt][kk][2] = pack_hi(p2); wlo[rt][kk][2] = pack_lo(p2);
            whi[rt][kk][3] = pack_hi(p3); wlo[rt][kk][3] = pack_lo(p3);
        }
    }

    // n-gate bias (multiplied by r in the cell, cannot be folded into gi)
    float bhn = 0.0f, h = 0.0f;
    float gir = 0.f, giz = 0.f, gin = 0.f;
    if (t < DD) {
        bhn = b_hh[t + 2 * DD];
        gir = g_gi[t]; giz = g_gi[t + DD]; gin = g_gi[t + 2 * DD];
        h_hi_s[t] = __float2bfloat16_rn(0.0f);
        h_lo_s[t] = __float2bfloat16_rn(0.0f);
    }
    __syncthreads();

    // --- B fragments (zeros for step 0; lanes >= 8 stay zero forever) ---
    uint32_t b[8][2];
    #pragma unroll
    for (int kk = 0; kk < 8; kk++) { b[kk][0] = 0u; b[kk][1] = 0u; }
    // (h is zero at step 0 so the zero-initialized fragments are already correct)

    for (int step = 0; step < NN; step++) {
        // ---- matvec: gh = W @ h on the tensor pipe ----
        float d[2][4];
        #pragma unroll
        for (int rt = 0; rt < 2; rt++)
            #pragma unroll
            for (int i = 0; i < 4; i++) d[rt][i] = 0.0f;

        #pragma unroll
        for (int kk = 0; kk < 8; kk++) {
            mma16816(d[0], whi[0][kk], b[kk]);
            mma16816(d[1], whi[1][kk], b[kk]);
        }
        #pragma unroll
        for (int kk = 0; kk < 8; kk++) {
            mma16816(d[0], wlo[0][kk], b[kk]);
            mma16816(d[1], wlo[1][kk], b[kk]);
        }

        // prefetch next step's gi while the tensor pipe drains
        float girn = 0.f, gizn = 0.f, ginn = 0.f;
        if (t < DD && step + 1 < NN) {
            const float* gp = g_gi + (step + 1) * 384;
            girn = gp[t]; gizn = gp[t + DD]; ginn = gp[t + 2 * DD];
        }

        if (qc == 0) {   // cols {0,1} = hi/lo products; sum = exact W@h row
            const int R = warp * 32 + qr;
            gh_s[R]      = d[0][0] + d[0][1];
            gh_s[R + 8]  = d[0][2] + d[0][3];
            gh_s[R + 16] = d[1][0] + d[1][1];
            gh_s[R + 24] = d[1][2] + d[1][3];
        }
        __syncthreads();

        // ---- gates + h update (threads 0..127) ----
        if (t < DD) {
            const float rr  = sig_acc(gir + gh_s[t]);          // b_hh_r folded in gi
            const float zz  = sig_acc(giz + gh_s[t + DD]);     // b_hh_z folded in gi
            const float nst = tanh_acc(gin + rr * (gh_s[t + 2 * DD] + bhn));
            h = (1.0f - zz) * nst + zz * h;
            out[step * DD + t] = h;
            const __nv_bfloat16 hh = __float2bfloat16_rn(h);
            h_hi_s[t] = hh;
            h_lo_s[t] = __float2bfloat16_rn(h - __bfloat162float(hh));
            gir = girn; giz = gizn; gin = ginn;
        }
        __syncthreads();

        // ---- rebuild B fragments from the new h (lanes 0-7 of every warp) ----
        if (lane < 8) {
            const __nv_bfloat16* src = (lane < 4) ? h_hi_s : h_lo_s;
            const int rbase = (lane & 3) * 2;
            #pragma unroll
            for (int kk = 0; kk < 8; kk++) {
                b[kk][0] = *(const uint32_t*)&src[kk * 16 + rbase];
                b[kk][1] = *(const uint32_t*)&src[kk * 16 + rbase + 8];
            }
        }
    }
}

// ---------------- launch ----------------
extern "C" void kernel_launch(void* const* d_in, const int* in_sizes, int n_in,
                              void* d_out, int out_size) {
    const float* X    = (const float*)d_in[0];
    const float* Wq   = (const float*)d_in[1];
    const float* Wk   = (const float*)d_in[2];
    const float* v    = (const float*)d_in[3];
    const float* w_ih = (const float*)d_in[4];
    const float* w_hh = (const float*)d_in[5];
    const float* b_ih = (const float*)d_in[6];
    const float* b_hh = (const float*)d_in[7];
    float* out = (float*)d_out;

    qk_kernel<<<NN / 8, 256>>>(X, Wq, Wk);
    att_kernel<<<NN / 4, 256>>>(X, v);
    gi_kernel<<<NN / 8, 384>>>(X, w_ih, b_ih, b_hh);
    gru_kernel<<<1, 384>>>(w_hh, b_hh, out);
}

// round 7
// speedup vs baseline: 2.1418x; 2.1418x over previous
#include <cuda_runtime.h>
#include <cuda_bf16.h>
#include <cstdint>

#define NN 1024
#define DD 128

// ---------------- scratch (no allocations allowed) ----------------
__device__ float g_q[NN * DD];
__device__ float g_k[NN * DD];
__device__ float g_att[NN * DD];
__device__ float g_gi[NN * 3 * DD];

// ---------------- helpers ----------------
__device__ __forceinline__ float tanh_apx(float x) {
    float y;
    asm("tanh.approx.f32 %0, %1;" : "=f"(y) : "f"(x));
    return y;
}

// accurate sigmoid/tanh for the GRU (errors compound over 1024 steps)
__device__ __forceinline__ float sig_acc(float x) {
    float e = __expf(-x);
    return __fdividef(1.0f, 1.0f + e);
}
__device__ __forceinline__ float tanh_acc(float x) {
    float e = __expf(-2.0f * x);
    return __fdividef(1.0f - e, 1.0f + e);
}

__device__ __forceinline__ unsigned long long ffma2(unsigned long long a,
                                                    unsigned long long b,
                                                    unsigned long long c) {
    unsigned long long d;
    asm("fma.rn.f32x2 %0, %1, %2, %3;" : "=l"(d) : "l"(a), "l"(b), "l"(c));
    return d;
}
__device__ __forceinline__ unsigned long long fadd2(unsigned long long a,
                                                    unsigned long long b) {
    unsigned long long d;
    asm("add.rn.f32x2 %0, %1, %2;" : "=l"(d) : "l"(a), "l"(b));
    return d;
}
__device__ __forceinline__ float f2lo(unsigned long long a) {
    return __uint_as_float((unsigned)(a & 0xffffffffull));
}
__device__ __forceinline__ float f2hi(unsigned long long a) {
    return __uint_as_float((unsigned)(a >> 32));
}

__device__ __forceinline__ float block_reduce_max(float v) {
    __shared__ float red[8];
    #pragma unroll
    for (int o = 16; o; o >>= 1) v = fmaxf(v, __shfl_xor_sync(0xffffffffu, v, o));
    if ((threadIdx.x & 31) == 0) red[threadIdx.x >> 5] = v;
    __syncthreads();
    float r = red[0];
    #pragma unroll
    for (int i = 1; i < 8; i++) r = fmaxf(r, red[i]);
    __syncthreads();
    return r;
}

__device__ __forceinline__ float block_reduce_sum(float v) {
    __shared__ float red[8];
    #pragma unroll
    for (int o = 16; o; o >>= 1) v += __shfl_xor_sync(0xffffffffu, v, o);
    if ((threadIdx.x & 31) == 0) red[threadIdx.x >> 5] = v;
    __syncthreads();
    float r = red[0];
    #pragma unroll
    for (int i = 1; i < 8; i++) r += red[i];
    __syncthreads();
    return r;
}

// ---------------- kernel 1: q = X@Wq^T, k = X@Wk^T ----------------
__global__ void __launch_bounds__(256) qk_kernel(const float* __restrict__ X,
                                                 const float* __restrict__ Wq,
                                                 const float* __restrict__ Wk) {
    __shared__ __align__(16) float xs[8][DD];
    const int n0 = blockIdx.x * 8;
    const int tid = threadIdx.x;
    for (int idx = tid; idx < 8 * DD; idx += 256)
        xs[idx >> 7][idx & 127] = X[(n0 + (idx >> 7)) * DD + (idx & 127)];
    __syncthreads();

    const int s = tid >> 7;
    const int d = tid & 127;
    const float4* W4 = (const float4*)((s ? Wk : Wq) + d * DD);
    float acc[8];
    #pragma unroll
    for (int r = 0; r < 8; r++) acc[r] = 0.0f;

    #pragma unroll 8
    for (int c = 0; c < 32; c++) {
        float4 w = W4[c];
        #pragma unroll
        for (int r = 0; r < 8; r++) {
            float4 x = *(const float4*)&xs[r][c * 4];
            acc[r] += w.x * x.x + w.y * x.y + w.z * x.z + w.w * x.w;
        }
    }
    float* dst = s ? g_k : g_q;
    #pragma unroll
    for (int r = 0; r < 8; r++) dst[(n0 + r) * DD + d] = acc[r];
}

// ---------------- kernel 2: attention (scores + softmax + att) ----------------
__global__ void __launch_bounds__(256) att_kernel(const float* __restrict__ X,
                                                  const float* __restrict__ v) {
    __shared__ __align__(16) float q_s[4][DD];
    __shared__ __align__(16) float v_s[DD];
    __shared__ float sc[4][NN];
    __shared__ float inv_s[4];
    __shared__ float part[4][DD];

    const int i0 = blockIdx.x * 4;
    const int tid = threadIdx.x;

    for (int idx = tid; idx < 4 * DD; idx += 256)
        q_s[idx >> 7][idx & 127] = g_q[(i0 + (idx >> 7)) * DD + (idx & 127)];
    if (tid < DD) v_s[tid] = v[tid];
    __syncthreads();

    for (int j = i0 + tid; j < NN; j += 256) {
        const float4* kr = (const float4*)(g_k + j * DD);
        float a0 = 0.f, a1 = 0.f, a2 = 0.f, a3 = 0.f;
        #pragma unroll 4
        for (int c = 0; c < 32; c++) {
            float4 kk = kr[c];
            float4 vv = *(const float4*)&v_s[c * 4];
            float4 q0 = *(const float4*)&q_s[0][c * 4];
            float4 q1 = *(const float4*)&q_s[1][c * 4];
            float4 q2 = *(const float4*)&q_s[2][c * 4];
            float4 q3 = *(const float4*)&q_s[3][c * 4];
            a0 += vv.x * tanh_apx(q0.x + kk.x) + vv.y * tanh_apx(q0.y + kk.y)
                + vv.z * tanh_apx(q0.z + kk.z) + vv.w * tanh_apx(q0.w + kk.w);
            a1 += vv.x * tanh_apx(q1.x + kk.x) + vv.y * tanh_apx(q1.y + kk.y)
                + vv.z * tanh_apx(q1.z + kk.z) + vv.w * tanh_apx(q1.w + kk.w);
            a2 += vv.x * tanh_apx(q2.x + kk.x) + vv.y * tanh_apx(q2.y + kk.y)
                + vv.z * tanh_apx(q2.z + kk.z) + vv.w * tanh_apx(q2.w + kk.w);
            a3 += vv.x * tanh_apx(q3.x + kk.x) + vv.y * tanh_apx(q3.y + kk.y)
                + vv.z * tanh_apx(q3.z + kk.z) + vv.w * tanh_apx(q3.w + kk.w);
        }
        const int jj = j - i0;
        sc[0][jj] = a0; sc[1][jj] = a1; sc[2][jj] = a2; sc[3][jj] = a3;
    }
    __syncthreads();

    const int L = NN - i0;
    for (int r = 0; r < 4; r++) {
        float m = -1e30f;
        for (int idx = tid; idx < L; idx += 256) m = fmaxf(m, sc[r][idx]);
        const float bm = block_reduce_max(m);
        float ssum = 0.f;
        for (int idx = tid; idx < L; idx += 256) {
            float e = (idx < r) ? 0.0f : __expf(sc[r][idx] - bm);
            sc[r][idx] = e;
            ssum += e;
        }
        const float bs = block_reduce_sum(ssum);
        if (tid == 0) inv_s[r] = 1.0f / bs;
    }
    __syncthreads();

    const int d = tid & 127;
    const int s2 = tid >> 7;
    float a[4] = {0.f, 0.f, 0.f, 0.f};
    for (int j = i0 + s2; j < NN; j += 2) {
        const float x = X[j * DD + d];
        const int jj = j - i0;
        a[0] += sc[0][jj] * x;
        a[1] += sc[1][jj] * x;
        a[2] += sc[2][jj] * x;
        a[3] += sc[3][jj] * x;
    }
    if (s2) {
        #pragma unroll
        for (int r = 0; r < 4; r++) part[r][d] = a[r];
    }
    __syncthreads();
    if (!s2) {
        #pragma unroll
        for (int r = 0; r < 4; r++)
            g_att[(i0 + r) * DD + d] = (a[r] + part[r][d]) * inv_s[r];
    }
}

// ---------------- kernel 3: gi = [X, att] @ w_ih^T + b_ih (+ b_hh fold) ----
// b_hh is additive for the r and z gates (rows 0..255), so fold it here.
// The n-gate bias multiplies by r inside the GRU, so it stays separate.
__global__ void __launch_bounds__(384) gi_kernel(const float* __restrict__ X,
                                                 const float* __restrict__ w_ih,
                                                 const float* __restrict__ b_ih,
                                                 const float* __restrict__ b_hh) {
    __shared__ __align__(16) float in_s[8][2 * DD];
    const int n0 = blockIdx.x * 8;
    const int tid = threadIdx.x;
    for (int idx = tid; idx < 8 * 2 * DD; idx += 384) {
        const int n = idx >> 8, e = idx & 255;
        in_s[n][e] = (e < DD) ? X[(n0 + n) * DD + e] : g_att[(n0 + n) * DD + (e - DD)];
    }
    __syncthreads();

    const float4* w4 = (const float4*)(w_ih + tid * (2 * DD));
    float acc[8];
    #pragma unroll
    for (int r = 0; r < 8; r++) acc[r] = 0.0f;

    #pragma unroll 4
    for (int c = 0; c < 64; c++) {
        float4 w = w4[c];
        #pragma unroll
        for (int r = 0; r < 8; r++) {
            float4 iv = *(const float4*)&in_s[r][c * 4];
            acc[r] += w.x * iv.x + w.y * iv.y + w.z * iv.z + w.w * iv.w;
        }
    }
    const float b = b_ih[tid] + ((tid < 2 * DD) ? b_hh[tid] : 0.0f);
    #pragma unroll
    for (int r = 0; r < 8; r++) g_gi[(n0 + r) * 384 + tid] = acc[r] + b;
}

// ---------------- kernel 4: sequential GRU (single CTA, FFMA2, role-inverted) -
// Warps 0-3  (t <  128): n-gate rows (w_hh row 256+t) + the serial tail.
// Warps 4-7  (t in [128,256)): r-gate rows (w_hh row t-128).
// Warps 8-11 (t in [256,384)): z-gate rows (w_hh row t-128).
// Hi-wid r/z warps finish the matvec first (arbiter priority), compute their
// sigmoid and bar.arrive(1) while the low-priority n-warps are still draining
// FFMA2s -> the sigmoid leaves the critical path. n-warps bar.sync(1), run the
// tail, everyone meets at bar.sync(2) before the next matvec.
__global__ void __launch_bounds__(384, 1) gru_kernel(const float* __restrict__ w_hh,
                                                     const float* __restrict__ b_hh,
                                                     float* __restrict__ out) {
    __shared__ __align__(16) float h_s[DD];
    __shared__ float r_s[DD];
    __shared__ float z_s[DD];

    const int t = threadIdx.x;
    const bool is_n = (t < DD);
    const int g = t & 127;
    const int wrow = is_n ? (2 * DD + t) : (t - DD);   // own w_hh / gi row

    unsigned long long w2[64];
    const unsigned long long* wp = (const unsigned long long*)(w_hh + wrow * DD);
    #pragma unroll
    for (int i = 0; i < 64; i++) w2[i] = wp[i];
    const float bh = is_n ? b_hh[2 * DD + t] : 0.0f;   // r/z bias folded in gi

    if (t < DD) h_s[t] = 0.0f;
    __syncthreads();

    const ulonglong2* h2 = (const ulonglong2*)h_s;

    float gi_cur = g_gi[wrow];   // step 0 gate input for this thread's own row

    for (int step = 0; step < NN; step++) {
        // prefetch next step's gi (hidden under the matvec)
        float gi_next = 0.0f;
        if (step + 1 < NN) gi_next = g_gi[(step + 1) * 384 + wrow];

        // s = bias + w_hh[wrow,:] . h   (packed f32x2 MACs, broadcast LDS of h)
        unsigned long long a0 = 0ull, a1 = 0ull, a2 = 0ull, a3 = 0ull;
        #pragma unroll
        for (int i = 0; i < 16; i++) {
            ulonglong2 hA = h2[2 * i];
            ulonglong2 hB = h2[2 * i + 1];
            a0 = ffma2(w2[4 * i + 0], hA.x, a0);
            a1 = ffma2(w2[4 * i + 1], hA.y, a1);
            a2 = ffma2(w2[4 * i + 2], hB.x, a2);
            a3 = ffma2(w2[4 * i + 3], hB.y, a3);
        }
        const unsigned long long p = fadd2(fadd2(a0, a1), fadd2(a2, a3));
        const float s = f2lo(p) + f2hi(p) + bh;

        if (!is_n) {
            // r/z warps: sigmoid locally, publish, arrive (non-blocking)
            const float val = sig_acc(gi_cur + s);
            if (t < 2 * DD) r_s[g] = val; else z_s[g] = val;
            asm volatile("bar.arrive 1, 384;" ::: "memory");
        } else {
            // n warps: wait for r/z, then the serial tail
            asm volatile("bar.sync 1, 384;" ::: "memory");
            const float rr  = r_s[g];
            const float zz  = z_s[g];
            const float nst = tanh_acc(gi_cur + rr * s);   // s includes b_hh_n
            const float hv  = (1.0f - zz) * nst + zz * h_s[g];
            out[step * DD + g] = hv;
            h_s[g] = hv;
        }
        // everyone: h must be written before the next matvec
        asm volatile("bar.sync 2, 384;" ::: "memory");
        gi_cur = gi_next;
    }
}

// ---------------- launch ----------------
extern "C" void kernel_launch(void* const* d_in, const int* in_sizes, int n_in,
                              void* d_out, int out_size) {
    const float* X    = (const float*)d_in[0];
    const float* Wq   = (const float*)d_in[1];
    const float* Wk   = (const float*)d_in[2];
    const float* v    = (const float*)d_in[3];
    const float* w_ih = (const float*)d_in[4];
    const float* w_hh = (const float*)d_in[5];
    const float* b_ih = (const float*)d_in[6];
    const float* b_hh = (const float*)d_in[7];
    float* out = (float*)d_out;

    qk_kernel<<<NN / 8, 256>>>(X, Wq, Wk);
    att_kernel<<<NN / 4, 256>>>(X, v);
    gi_kernel<<<NN / 8, 384>>>(X, w_ih, b_ih, b_hh);
    gru_kernel<<<1, 384>>>(w_hh, b_hh, out);
}

// round 8
// speedup vs baseline: 2.3057x; 1.0765x over previous
#include <cuda_runtime.h>
#include <cuda_bf16.h>
#include <cstdint>

#define NN 1024
#define DD 128

// ---------------- scratch (no allocations allowed) ----------------
__device__ float g_q[NN * DD];
__device__ float g_k[NN * DD];
__device__ float g_att[NN * DD];
__device__ float g_gi[NN * 3 * DD];

// progress flags for gi->gru overlap (epoch-valued, monotonic => replay-safe)
__device__ int g_flag[132];          // g_flag[c] == epoch when gi chunk c (8 rows) ready
__device__ int g_epoch_gi[NN / 8];   // per-gi-CTA launch counters
__device__ int g_epoch_gru;          // gru launch counter

// ---------------- helpers ----------------
__device__ __forceinline__ float tanh_apx(float x) {
    float y;
    asm("tanh.approx.f32 %0, %1;" : "=f"(y) : "f"(x));
    return y;
}
// sigmoid via one MUFU tanh (abs err ~1e-5; GRU is strongly contracting)
__device__ __forceinline__ float sig_apx(float x) {
    return fmaf(0.5f, tanh_apx(0.5f * x), 0.5f);
}

__device__ __forceinline__ unsigned long long ffma2(unsigned long long a,
                                                    unsigned long long b,
                                                    unsigned long long c) {
    unsigned long long d;
    asm("fma.rn.f32x2 %0, %1, %2, %3;" : "=l"(d) : "l"(a), "l"(b), "l"(c));
    return d;
}
__device__ __forceinline__ unsigned long long fadd2(unsigned long long a,
                                                    unsigned long long b) {
    unsigned long long d;
    asm("add.rn.f32x2 %0, %1, %2;" : "=l"(d) : "l"(a), "l"(b));
    return d;
}
__device__ __forceinline__ float f2lo(unsigned long long a) {
    return __uint_as_float((unsigned)(a & 0xffffffffull));
}
__device__ __forceinline__ float f2hi(unsigned long long a) {
    return __uint_as_float((unsigned)(a >> 32));
}

__device__ __forceinline__ float block_reduce_max(float v) {
    __shared__ float red[8];
    #pragma unroll
    for (int o = 16; o; o >>= 1) v = fmaxf(v, __shfl_xor_sync(0xffffffffu, v, o));
    if ((threadIdx.x & 31) == 0) red[threadIdx.x >> 5] = v;
    __syncthreads();
    float r = red[0];
    #pragma unroll
    for (int i = 1; i < 8; i++) r = fmaxf(r, red[i]);
    __syncthreads();
    return r;
}

__device__ __forceinline__ float block_reduce_sum(float v) {
    __shared__ float red[8];
    #pragma unroll
    for (int o = 16; o; o >>= 1) v += __shfl_xor_sync(0xffffffffu, v, o);
    if ((threadIdx.x & 31) == 0) red[threadIdx.x >> 5] = v;
    __syncthreads();
    float r = red[0];
    #pragma unroll
    for (int i = 1; i < 8; i++) r += red[i];
    __syncthreads();
    return r;
}

// ---------------- kernel 1: q = X@Wq^T, k = X@Wk^T ----------------
__global__ void __launch_bounds__(256) qk_kernel(const float* __restrict__ X,
                                                 const float* __restrict__ Wq,
                                                 const float* __restrict__ Wk) {
    __shared__ __align__(16) float xs[8][DD];
    const int n0 = blockIdx.x * 8;
    const int tid = threadIdx.x;
    for (int idx = tid; idx < 8 * DD; idx += 256)
        xs[idx >> 7][idx & 127] = X[(n0 + (idx >> 7)) * DD + (idx & 127)];
    __syncthreads();

    const int s = tid >> 7;
    const int d = tid & 127;
    const float4* W4 = (const float4*)((s ? Wk : Wq) + d * DD);
    float acc[8];
    #pragma unroll
    for (int r = 0; r < 8; r++) acc[r] = 0.0f;

    #pragma unroll 8
    for (int c = 0; c < 32; c++) {
        float4 w = W4[c];
        #pragma unroll
        for (int r = 0; r < 8; r++) {
            float4 x = *(const float4*)&xs[r][c * 4];
            acc[r] += w.x * x.x + w.y * x.y + w.z * x.z + w.w * x.w;
        }
    }
    float* dst = s ? g_k : g_q;
    #pragma unroll
    for (int r = 0; r < 8; r++) dst[(n0 + r) * DD + d] = acc[r];
}

// ---------------- kernel 2: attention (scores + softmax + att) ----------------
__global__ void __launch_bounds__(256) att_kernel(const float* __restrict__ X,
                                                  const float* __restrict__ v) {
    __shared__ __align__(16) float q_s[4][DD];
    __shared__ __align__(16) float v_s[DD];
    __shared__ float sc[4][NN];
    __shared__ float inv_s[4];
    __shared__ float part[4][DD];

    const int i0 = blockIdx.x * 4;
    const int tid = threadIdx.x;

    for (int idx = tid; idx < 4 * DD; idx += 256)
        q_s[idx >> 7][idx & 127] = g_q[(i0 + (idx >> 7)) * DD + (idx & 127)];
    if (tid < DD) v_s[tid] = v[tid];
    __syncthreads();

    for (int j = i0 + tid; j < NN; j += 256) {
        const float4* kr = (const float4*)(g_k + j * DD);
        float a0 = 0.f, a1 = 0.f, a2 = 0.f, a3 = 0.f;
        #pragma unroll 4
        for (int c = 0; c < 32; c++) {
            float4 kk = kr[c];
            float4 vv = *(const float4*)&v_s[c * 4];
            float4 q0 = *(const float4*)&q_s[0][c * 4];
            float4 q1 = *(const float4*)&q_s[1][c * 4];
            float4 q2 = *(const float4*)&q_s[2][c * 4];
            float4 q3 = *(const float4*)&q_s[3][c * 4];
            a0 += vv.x * tanh_apx(q0.x + kk.x) + vv.y * tanh_apx(q0.y + kk.y)
                + vv.z * tanh_apx(q0.z + kk.z) + vv.w * tanh_apx(q0.w + kk.w);
            a1 += vv.x * tanh_apx(q1.x + kk.x) + vv.y * tanh_apx(q1.y + kk.y)
                + vv.z * tanh_apx(q1.z + kk.z) + vv.w * tanh_apx(q1.w + kk.w);
            a2 += vv.x * tanh_apx(q2.x + kk.x) + vv.y * tanh_apx(q2.y + kk.y)
                + vv.z * tanh_apx(q2.z + kk.z) + vv.w * tanh_apx(q2.w + kk.w);
            a3 += vv.x * tanh_apx(q3.x + kk.x) + vv.y * tanh_apx(q3.y + kk.y)
                + vv.z * tanh_apx(q3.z + kk.z) + vv.w * tanh_apx(q3.w + kk.w);
        }
        const int jj = j - i0;
        sc[0][jj] = a0; sc[1][jj] = a1; sc[2][jj] = a2; sc[3][jj] = a3;
    }
    __syncthreads();

    const int L = NN - i0;
    for (int r = 0; r < 4; r++) {
        float m = -1e30f;
        for (int idx = tid; idx < L; idx += 256) m = fmaxf(m, sc[r][idx]);
        const float bm = block_reduce_max(m);
        float ssum = 0.f;
        for (int idx = tid; idx < L; idx += 256) {
            float e = (idx < r) ? 0.0f : __expf(sc[r][idx] - bm);
            sc[r][idx] = e;
            ssum += e;
        }
        const float bs = block_reduce_sum(ssum);
        if (tid == 0) inv_s[r] = 1.0f / bs;
    }
    __syncthreads();

    const int d = tid & 127;
    const int s2 = tid >> 7;
    float a[4] = {0.f, 0.f, 0.f, 0.f};
    for (int j = i0 + s2; j < NN; j += 2) {
        const float x = X[j * DD + d];
        const int jj = j - i0;
        a[0] += sc[0][jj] * x;
        a[1] += sc[1][jj] * x;
        a[2] += sc[2][jj] * x;
        a[3] += sc[3][jj] * x;
    }
    if (s2) {
        #pragma unroll
        for (int r = 0; r < 4; r++) part[r][d] = a[r];
    }
    __syncthreads();
    if (!s2) {
        #pragma unroll
        for (int r = 0; r < 4; r++)
            g_att[(i0 + r) * DD + d] = (a[r] + part[r][d]) * inv_s[r];
    }
}

// ---------------- kernel 3: gi = [X, att] @ w_ih^T + b_ih (+ b_hh fold) ----
// Publishes an epoch flag per 8-row chunk so the overlapped GRU can consume
// progressively. Epochs are per-CTA launch counters: monotonic, so no reset
// is needed across graph replays.
__global__ void __launch_bounds__(384) gi_kernel(const float* __restrict__ X,
                                                 const float* __restrict__ w_ih,
                                                 const float* __restrict__ b_ih,
                                                 const float* __restrict__ b_hh) {
    __shared__ __align__(16) float in_s[8][2 * DD];
    const int blk = blockIdx.x;
    const int n0 = blk * 8;
    const int tid = threadIdx.x;

    int my_epoch = 0;
    if (tid == 0) my_epoch = atomicAdd(&g_epoch_gi[blk], 1) + 1;

    for (int idx = tid; idx < 8 * 2 * DD; idx += 384) {
        const int n = idx >> 8, e = idx & 255;
        in_s[n][e] = (e < DD) ? X[(n0 + n) * DD + e] : g_att[(n0 + n) * DD + (e - DD)];
    }
    __syncthreads();

    const float4* w4 = (const float4*)(w_ih + tid * (2 * DD));
    float acc[8];
    #pragma unroll
    for (int r = 0; r < 8; r++) acc[r] = 0.0f;

    #pragma unroll 4
    for (int c = 0; c < 64; c++) {
        float4 w = w4[c];
        #pragma unroll
        for (int r = 0; r < 8; r++) {
            float4 iv = *(const float4*)&in_s[r][c * 4];
            acc[r] += w.x * iv.x + w.y * iv.y + w.z * iv.z + w.w * iv.w;
        }
    }
    const float b = b_ih[tid] + ((tid < 2 * DD) ? b_hh[tid] : 0.0f);
    #pragma unroll
    for (int r = 0; r < 8; r++) g_gi[(n0 + r) * 384 + tid] = acc[r] + b;

    // publish: all rows of this chunk are in global memory
    __threadfence();
    __syncthreads();
    if (tid == 0) *(volatile int*)&g_flag[blk] = my_epoch;
}

// ---------------- kernel 4: sequential GRU (overlapped consumer) -------------
// Warps 0-3  (t <  128): n-gate rows + serial tail.
// Warps 4-11 (t >= 128): r/z-gate rows, sigmoid pre-barrier.
// Polls gi chunk flags every 32 steps (window +4 chunks covers the prefetch).
__global__ void __launch_bounds__(384, 1) gru_kernel(const float* __restrict__ w_hh,
                                                     const float* __restrict__ b_hh,
                                                     float* __restrict__ out) {
    __shared__ __align__(16) float h_s[DD];
    __shared__ float r_s[DD];
    __shared__ float z_s[DD];
    __shared__ int epoch_s;

    const int t = threadIdx.x;
    const bool is_n = (t < DD);
    const int g = t & 127;
    const int wrow = is_n ? (2 * DD + t) : (t - DD);   // own w_hh / gi row

    if (t == 0) epoch_s = atomicAdd(&g_epoch_gru, 1) + 1;

    unsigned long long w2[64];
    const unsigned long long* wp = (const unsigned long long*)(w_hh + wrow * DD);
    #pragma unroll
    for (int i = 0; i < 64; i++) w2[i] = wp[i];
    const float bh = is_n ? b_hh[2 * DD + t] : 0.0f;   // r/z bias folded in gi

    if (t < DD) h_s[t] = 0.0f;
    __syncthreads();
    const int epoch = epoch_s;

    const ulonglong2* h2 = (const ulonglong2*)h_s;

    // wait for gi chunks 0..4 (covers steps 0..31 plus the +1 prefetch)
    {
        volatile int* f = g_flag;
        while (f[0] < epoch || f[1] < epoch || f[2] < epoch ||
               f[3] < epoch || f[4] < epoch)
            __nanosleep(64);
    }
    float gi_cur = g_gi[wrow];   // step 0 gate input for this thread's own row

    for (int step = 0; step < NN; step++) {
        if ((step & 31) == 0 && step) {
            const int c0 = step >> 3;
            const int c4 = (c0 + 4 < 128) ? (c0 + 4) : 127;
            volatile int* f = g_flag;
            while (f[c0] < epoch || f[c0 + 1] < epoch || f[c0 + 2] < epoch ||
                   f[c0 + 3] < epoch || f[c4] < epoch)
                __nanosleep(64);
        }

        // prefetch next step's gi (hidden under the matvec)
        float gi_next = 0.0f;
        if (step + 1 < NN) gi_next = g_gi[(step + 1) * 384 + wrow];

        // s = bias + w_hh[wrow,:] . h   (packed f32x2 MACs, broadcast LDS of h)
        unsigned long long a0 = 0ull, a1 = 0ull, a2 = 0ull, a3 = 0ull;
        #pragma unroll
        for (int i = 0; i < 16; i++) {
            ulonglong2 hA = h2[2 * i];
            ulonglong2 hB = h2[2 * i + 1];
            a0 = ffma2(w2[4 * i + 0], hA.x, a0);
            a1 = ffma2(w2[4 * i + 1], hA.y, a1);
            a2 = ffma2(w2[4 * i + 2], hB.x, a2);
            a3 = ffma2(w2[4 * i + 3], hB.y, a3);
        }
        const unsigned long long p = fadd2(fadd2(a0, a1), fadd2(a2, a3));
        const float s = f2lo(p) + f2hi(p) + bh;

        if (!is_n) {
            // r/z warps: sigmoid locally, publish, arrive (non-blocking)
            const float val = sig_apx(gi_cur + s);
            if (t < 2 * DD) r_s[g] = val; else z_s[g] = val;
            asm volatile("bar.arrive 1, 384;" ::: "memory");
        } else {
            // n warps: wait for r/z, then the serial tail
            asm volatile("bar.sync 1, 384;" ::: "memory");
            const float rr  = r_s[g];
            const float zz  = z_s[g];
            const float nst = tanh_apx(fmaf(rr, s, gi_cur));   // s includes b_hh_n
            const float hv  = fmaf(zz, h_s[g] - nst, nst);     // (1-z)n + z h
            out[step * DD + g] = hv;
            h_s[g] = hv;
        }
        // everyone: h must be written before the next matvec
        asm volatile("bar.sync 2, 384;" ::: "memory");
        gi_cur = gi_next;
    }
}

// ---------------- launch ----------------
extern "C" void kernel_launch(void* const* d_in, const int* in_sizes, int n_in,
                              void* d_out, int out_size) {
    const float* X    = (const float*)d_in[0];
    const float* Wq   = (const float*)d_in[1];
    const float* Wk   = (const float*)d_in[2];
    const float* v    = (const float*)d_in[3];
    const float* w_ih = (const float*)d_in[4];
    const float* w_hh = (const float*)d_in[5];
    const float* b_ih = (const float*)d_in[6];
    const float* b_hh = (const float*)d_in[7];
    float* out = (float*)d_out;

    // fork: prologue (qk -> att -> gi) on a side stream, GRU starts immediately
    // on the main stream and consumes gi chunks via epoch flags.
    cudaStream_t s2;
    cudaStreamCreateWithFlags(&s2, cudaStreamNonBlocking);
    cudaEvent_t e1, e2;
    cudaEventCreateWithFlags(&e1, cudaEventDisableTiming);
    cudaEventCreateWithFlags(&e2, cudaEventDisableTiming);

    cudaEventRecord(e1, 0);
    cudaStreamWaitEvent(s2, e1, 0);

    qk_kernel<<<NN / 8, 256, 0, s2>>>(X, Wq, Wk);
    att_kernel<<<NN / 4, 256, 0, s2>>>(X, v);
    gi_kernel<<<NN / 8, 384, 0, s2>>>(X, w_ih, b_ih, b_hh);
    cudaEventRecord(e2, s2);

    gru_kernel<<<1, 384>>>(w_hh, b_hh, out);

    cudaStreamWaitEvent(0, e2, 0);
}